// round 15
// baseline (speedup 1.0000x reference)
#include <cuda_runtime.h>
#include <cuda_fp16.h>
#include <cstdint>

#define B_MAX 65536

// ---------------- device scratch (no allocs allowed) ----------------
// repacked weights fp16: [l][khalf][n'=4j+gate : 256][kc : 72 (64+pad)]
// khalf 0 = recurrent (k 0..63), khalf 1 = input (k 64..127; zero for l==0)
__device__ __align__(16) __half g_wm[4][2][256][72];
__device__ float g_init[(size_t)B_MAX * 128];   // [b][128] = (h0 | c0)

// ---------------- math (HW tanh; sigmoid via tanh identity) ----------------
__device__ __forceinline__ float tanh_(float x) {
    float y; asm("tanh.approx.f32 %0, %1;" : "=f"(y) : "f"(x)); return y;
}
__device__ __forceinline__ float sigm(float x) {
    return fmaf(tanh_(0.5f * x), 0.5f, 0.5f);
}

// ---------------- PTX helpers (portable sm_80+) ----------------
__device__ __forceinline__ uint32_t s32(const void* p) { return (uint32_t)__cvta_generic_to_shared(p); }
__device__ __forceinline__ void cp16(uint32_t dst, const void* src) {
    asm volatile("cp.async.cg.shared.global [%0], [%1], 16;" :: "r"(dst), "l"(src));
}
__device__ __forceinline__ void cp_commit() { asm volatile("cp.async.commit_group;" ::: "memory"); }
__device__ __forceinline__ void cp_wait0()  { asm volatile("cp.async.wait_group 0;" ::: "memory"); }
__device__ __forceinline__ void cp_wait1()  { asm volatile("cp.async.wait_group 1;" ::: "memory"); }

__device__ __forceinline__ void ldsm4(uint32_t r[4], uint32_t addr) {
    asm volatile("ldmatrix.sync.aligned.m8n8.x4.shared.b16 {%0,%1,%2,%3}, [%4];"
        : "=r"(r[0]), "=r"(r[1]), "=r"(r[2]), "=r"(r[3]) : "r"(addr));
}
__device__ __forceinline__ void mma16816(float d[4], const uint32_t a[4], uint32_t b0, uint32_t b1) {
    asm volatile("mma.sync.aligned.m16n8k16.row.col.f32.f16.f16.f32 "
        "{%0,%1,%2,%3}, {%4,%5,%6,%7}, {%8,%9}, {%0,%1,%2,%3};"
        : "+f"(d[0]), "+f"(d[1]), "+f"(d[2]), "+f"(d[3])
        : "r"(a[0]), "r"(a[1]), "r"(a[2]), "r"(a[3]), "r"(b0), "r"(b1));
}

// ---------------- SMEM layout (bytes from 1024-aligned base) ----------------
#define W_HALF 36864      // 256 rows x 144B
#define OFF_H    0        // h: [l:4][m:64][k:72] fp16 = 36864 (144B rows)
#define OFF_W    36864    // bufA + bufB = 73728
#define OFF_BIAS 110592   // [4][256] f32 (n'=4j+g order) = 4096
#define OFF_WI0  114688   // [256][3] f32 = 3072
#define OFF_WO   117760   // [3][64] f32 = 768
#define OFF_BO   118528   // 16
#define OFF_X    118544   // [3][64] f32 = 768
#define SMEM_USE 119312
#define SMEM_REQ (SMEM_USE + 1024)

// ---------------- single prologue: weight repack + decoder_fc ----------------
__global__ void prologue_k(const float* __restrict__ conds,
                           const float* __restrict__ W1, const float* __restrict__ b1,
                           const float* __restrict__ W2, const float* __restrict__ b2,
                           const float* __restrict__ W_hh, const float* __restrict__ W_ih_rest) {
    const int b = blockIdx.x;
    const int t = threadIdx.x;  // 128

    // ---- repack slice (blocks 0..1151) ----
    int idx = b * 128 + t;
    if (idx < 4 * 2 * 256 * 72) {
        int kc = idx % 72, r = (idx / 72) & 255;
        int half = (idx / (72 * 256)) & 1, l = idx / (72 * 512);
        float v = 0.f;
        if (kc < 64) {
            int j = r >> 2, g = r & 3, n = g * 64 + j;
            if (half == 0)    v = W_hh[(l * 256 + n) * 64 + kc];
            else if (l > 0)   v = W_ih_rest[((l - 1) * 256 + n) * 64 + kc];
        }
        g_wm[l][half][r][kc] = __float2half(v);
    }

    // ---- embed for batch row b ----
    __shared__ float hid[64];
    __shared__ float cnd[8];
    if (t < 8) cnd[t] = conds[b * 8 + t];
    __syncthreads();
    if (t < 64) {
        float a = b1[t];
        #pragma unroll
        for (int k = 0; k < 8; k++) a += cnd[k] * W1[t * 8 + k];
        hid[t] = fmaxf(a, 0.f);
    }
    __syncthreads();
    float a = b2[t];
    #pragma unroll
    for (int k = 0; k < 64; k++) a += hid[k] * W2[t * 64 + k];
    g_init[(size_t)b * 128 + t] = a;
}

// stage one W half-image (36864 B) — all 512 threads
__device__ __forceinline__ void stageWh(uint32_t dst, int l, int half, int tid) {
    const char* src = (const char*)&g_wm[l][half][0][0];
    #pragma unroll
    for (int n = 0; n < 4; n++)
        cp16(dst + (uint32_t)(tid * 16 + n * 8192), src + tid * 16 + n * 8192);
    if (tid < 256) cp16(dst + (uint32_t)(32768 + tid * 16), src + 32768 + tid * 16);
    cp_commit();
}

// One K=64 block: A = 32 rows of h (2 m-tiles), B = 32 W rows (2 n-tiles).
#define CHUNK1(ABASE, WBASE)                                                           \
{                                                                                      \
    _Pragma("unroll")                                                                  \
    for (int ki = 0; ki < 4; ki++) {                                                   \
        uint32_t ah_[2][4];                                                            \
        _Pragma("unroll")                                                              \
        for (int mt = 0; mt < 2; mt++)                                                 \
            ldsm4(ah_[mt], (ABASE) + (uint32_t)((m0w + mt * 16) * 144 + ki * 32) + laneoff); \
        _Pragma("unroll")                                                              \
        for (int nt2 = 0; nt2 < 2; nt2++) {                                            \
            uint32_t bf_[4];                                                           \
            ldsm4(bf_, (WBASE) + (uint32_t)((n0w + nt2 * 16) * 144 + ki * 32) + laneoff); \
            _Pragma("unroll")                                                          \
            for (int mt = 0; mt < 2; mt++) {                                           \
                mma16816(acc[mt][2 * nt2],     ah_[mt], bf_[0], bf_[2]);               \
                mma16816(acc[mt][2 * nt2 + 1], ah_[mt], bf_[1], bf_[3]);               \
            }                                                                          \
        }                                                                              \
    }                                                                                  \
}

// Register-resident epilogue for layer L: shuffle-gather gates, activate,
// update c (CR[8], idx = mt*4+nq), store h fp16.
#define EPI(L, CR)                                                                     \
{                                                                                      \
    _Pragma("unroll")                                                                  \
    for (int mt = 0; mt < 2; mt++)                                                     \
        _Pragma("unroll")                                                              \
        for (int nq = 0; nq < 4; nq++) {                                               \
            float a0 = acc[mt][nq][0], a1 = acc[mt][nq][1];                            \
            float a2 = acc[mt][nq][2], a3 = acc[mt][nq][3];                            \
            float s1 = (tig & 1) ? a0 : a2;                                            \
            float s2 = (tig & 1) ? a1 : a3;                                            \
            float r1 = __shfl_xor_sync(0xFFFFFFFFu, s1, 1);                            \
            float r2 = __shfl_xor_sync(0xFFFFFFFFu, s2, 1);                            \
            int j = (n0w + nq * 8 + 2 * tig) >> 2;                                     \
            int row; float vi, vf, vg, vo;                                             \
            if ((tig & 1) == 0) { row = m0w + mt * 16 + gid;     vi = a0; vf = a1; vg = r1; vo = r2; } \
            else                { row = m0w + mt * 16 + gid + 8; vi = r1; vf = r2; vg = a2; vo = a3; } \
            if ((L) == 0) {                                                            \
                float x0 = xS[row], x1 = xS[64 + row], x2 = xS[128 + row];             \
                vi += x0 * wi0S[j * 3]         + x1 * wi0S[j * 3 + 1]         + x2 * wi0S[j * 3 + 2];         \
                vf += x0 * wi0S[(64 + j) * 3]  + x1 * wi0S[(64 + j) * 3 + 1]  + x2 * wi0S[(64 + j) * 3 + 2];  \
                vg += x0 * wi0S[(128 + j) * 3] + x1 * wi0S[(128 + j) * 3 + 1] + x2 * wi0S[(128 + j) * 3 + 2]; \
                vo += x0 * wi0S[(192 + j) * 3] + x1 * wi0S[(192 + j) * 3 + 1] + x2 * wi0S[(192 + j) * 3 + 2]; \
            }                                                                          \
            float cn = sigm(vf) * CR[mt * 4 + nq] + sigm(vi) * tanh_(vg);              \
            CR[mt * 4 + nq] = cn;                                                      \
            float hn = sigm(vo) * tanh_(cn);                                           \
            hE[((L) * 64 + row) * 72 + j] = __float2half(hn);                          \
        }                                                                              \
}

__global__ __launch_bounds__(512, 1)
void lstm_main(const float* __restrict__ b_ih, const float* __restrict__ b_hh,
               const float* __restrict__ W_ih0,
               const float* __restrict__ Wo, const float* __restrict__ bo,
               float* __restrict__ out, int T) {
    extern __shared__ char raw[];
    char* basep = (char*)(((uintptr_t)raw + 1023) & ~(uintptr_t)1023);
    const uint32_t hS  = s32(basep + OFF_H);
    const uint32_t wA  = s32(basep + OFF_W);
    const uint32_t wB  = wA + W_HALF;
    __half* hE   = (__half*)(basep + OFF_H);
    float* biasS = (float*)(basep + OFF_BIAS);
    float* wi0S  = (float*)(basep + OFF_WI0);
    float* woS   = (float*)(basep + OFF_WO);
    float* boS   = (float*)(basep + OFF_BO);
    float* xS    = (float*)(basep + OFF_X);

    const int tid = threadIdx.x;
    const int bb0 = blockIdx.x * 64;
    const int lane = tid & 31, wid = tid >> 5;
    const int m0w = (wid & 1) * 32;          // 2 m-groups
    const int n0w = (wid >> 1) * 32;         // 8 n-groups (units j = n0w/4 .. +7)
    const int sel = lane >> 3, lrow = lane & 7;
    const uint32_t laneoff = (uint32_t)(((sel & 1) * 8 + lrow) * 144 + (sel >> 1) * 16);
    const int gid = lane >> 2, tig = lane & 3;

    // ---- stage small params ----
    for (int i = tid; i < 1024; i += 512) {
        int l = i >> 8, n = i & 255, g = n >> 6, j = n & 63;
        biasS[l * 256 + 4 * j + g] = b_ih[i] + b_hh[i];
    }
    for (int i = tid; i < 768;  i += 512) wi0S[i] = W_ih0[i];
    if (tid < 192) woS[tid] = Wo[tid];
    if (tid < 3)   boS[tid] = bo[tid];
    if (tid < 64)  { xS[tid] = 0.5f; xS[64 + tid] = 0.5f; xS[128 + tid] = 0.f; }

    // ---- init c (regs, cell mapping == EPI) and h (fp16, all layers) ----
    float cr0[8], cr1[8], cr2[8], cr3[8];
    #pragma unroll
    for (int mt = 0; mt < 2; mt++)
        #pragma unroll
        for (int nq = 0; nq < 4; nq++) {
            int j = (n0w + nq * 8 + 2 * tig) >> 2;
            int row = m0w + mt * 16 + gid + ((tig & 1) ? 8 : 0);
            float hv = g_init[(size_t)(bb0 + row) * 128 + j];
            float cv = g_init[(size_t)(bb0 + row) * 128 + 64 + j];
            cr0[mt * 4 + nq] = cv; cr1[mt * 4 + nq] = cv;
            cr2[mt * 4 + nq] = cv; cr3[mt * 4 + nq] = cv;
            __half bh = __float2half(hv);
            #pragma unroll
            for (int l = 0; l < 4; l++) hE[(l * 64 + row) * 72 + j] = bh;
        }

    // prime weight pipeline: A(0), B(0) -> 2 groups outstanding per thread
    stageWh(wA, 0, 0, tid);
    stageWh(wB, 0, 1, tid);
    __syncthreads();

    for (int t = 0; t < T; t++) {
        for (int l = 0; l < 4; l++) {
            const bool last = (t == T - 1 && l == 3);
            const int lnxt = (l + 1) & 3;

            cp_wait1();                 // A(l) resident (outstanding: B(l))
            __syncthreads();            // + prev-layer h stores visible

            // acc init = bias
            float acc[2][4][4];
            #pragma unroll
            for (int nq = 0; nq < 4; nq++) {
                int col = n0w + nq * 8 + 2 * tig;
                float b0 = biasS[l * 256 + col];
                float b1 = biasS[l * 256 + col + 1];
                #pragma unroll
                for (int mt = 0; mt < 2; mt++) {
                    acc[mt][nq][0] = b0; acc[mt][nq][1] = b1;
                    acc[mt][nq][2] = b0; acc[mt][nq][3] = b1;
                }
            }

            // recurrent half: A = h[l] (t-1)
            CHUNK1(hS + (uint32_t)(l * 9216), wA);
            __syncthreads();            // all done reading bufA
            if (!last) stageWh(wA, lnxt, 0, tid);

            if (last) cp_wait0(); else cp_wait1();   // B(l) resident
            __syncthreads();

            // input half: A = h[l-1] (fresh this step)
            if (l > 0)
                CHUNK1(hS + (uint32_t)((l - 1) * 9216), wB);
            __syncthreads();            // all done reading bufB
            if (!last) stageWh(wB, lnxt, 1, tid);

            // register epilogue (writes h[l])
            switch (l) {
                case 0: EPI(0, cr0); break;
                case 1: EPI(1, cr1); break;
                case 2: EPI(2, cr2); break;
                default: EPI(3, cr3); break;
            }

            if (l == 3) {
                __syncthreads();        // h3 visible
                if (tid < 192) {
                    int jo = tid >> 6, b = tid & 63;
                    float a = boS[jo];
                    #pragma unroll 8
                    for (int j = 0; j < 64; j++)
                        a += woS[jo * 64 + j] * __half2float(hE[(192 + b) * 72 + j]);
                    out[(size_t)(bb0 + b) * (3 * T) + (size_t)t * 3 + jo] = a;
                    xS[jo * 64 + b] = a;
                }
            }
        }
    }
}

// ---------------- entry ----------------
extern "C" void kernel_launch(void* const* d_in, const int* in_sizes, int n_in,
                              void* d_out, int out_size) {
    const float* conds     = (const float*)d_in[0];
    const float* W1        = (const float*)d_in[1];
    const float* b1        = (const float*)d_in[2];
    const float* W2        = (const float*)d_in[3];
    const float* b2        = (const float*)d_in[4];
    const float* W_ih0     = (const float*)d_in[5];
    const float* W_ih_rest = (const float*)d_in[6];
    const float* W_hh      = (const float*)d_in[7];
    const float* b_ih      = (const float*)d_in[8];
    const float* b_hh      = (const float*)d_in[9];
    const float* Wo        = (const float*)d_in[10];
    const float* bo        = (const float*)d_in[11];

    int B = in_sizes[0] / 8;
    if (B > B_MAX) B = B_MAX;
    int T = out_size / (B * 3);

    cudaFuncSetAttribute(lstm_main, cudaFuncAttributeMaxDynamicSharedMemorySize, SMEM_REQ);

    prologue_k<<<B, 128>>>(conds, W1, b1, W2, b2, W_hh, W_ih_rest);
    lstm_main<<<B / 64, 512, SMEM_REQ>>>(b_ih, b_hh, W_ih0, Wo, bo, (float*)d_out, T);
}

// round 16
// speedup vs baseline: 1.0610x; 1.0610x over previous
#include <cuda_runtime.h>
#include <cuda_fp16.h>
#include <cstdint>

#define B_MAX 65536

// ---------------- device scratch (no allocs allowed) ----------------
// repacked weights fp16: [l][khalf][n'=4j+gate : 256][kc : 72 (64+pad)]
// khalf 0 = recurrent (k 0..63), khalf 1 = input (k 64..127; zero for l==0)
__device__ __align__(16) __half g_wm[4][2][256][72];
__device__ float g_init[(size_t)B_MAX * 128];   // [b][128] = (h0 | c0)

// ---------------- math (HW tanh; sigmoid via tanh identity) ----------------
__device__ __forceinline__ float tanh_(float x) {
    float y; asm("tanh.approx.f32 %0, %1;" : "=f"(y) : "f"(x)); return y;
}
__device__ __forceinline__ float sigm(float x) {
    return fmaf(tanh_(0.5f * x), 0.5f, 0.5f);
}

// ---------------- PTX helpers (portable sm_80+) ----------------
__device__ __forceinline__ uint32_t s32(const void* p) { return (uint32_t)__cvta_generic_to_shared(p); }
__device__ __forceinline__ void cp16(uint32_t dst, const void* src) {
    asm volatile("cp.async.cg.shared.global [%0], [%1], 16;" :: "r"(dst), "l"(src));
}
__device__ __forceinline__ void cp_commit() { asm volatile("cp.async.commit_group;" ::: "memory"); }
__device__ __forceinline__ void cp_wait0()  { asm volatile("cp.async.wait_group 0;" ::: "memory"); }
__device__ __forceinline__ void cp_wait1()  { asm volatile("cp.async.wait_group 1;" ::: "memory"); }

__device__ __forceinline__ void ldsm4(uint32_t r[4], uint32_t addr) {
    asm volatile("ldmatrix.sync.aligned.m8n8.x4.shared.b16 {%0,%1,%2,%3}, [%4];"
        : "=r"(r[0]), "=r"(r[1]), "=r"(r[2]), "=r"(r[3]) : "r"(addr));
}
__device__ __forceinline__ void mma16816(float d[4], const uint32_t a[4], uint32_t b0, uint32_t b1) {
    asm volatile("mma.sync.aligned.m16n8k16.row.col.f32.f16.f16.f32 "
        "{%0,%1,%2,%3}, {%4,%5,%6,%7}, {%8,%9}, {%0,%1,%2,%3};"
        : "+f"(d[0]), "+f"(d[1]), "+f"(d[2]), "+f"(d[3])
        : "r"(a[0]), "r"(a[1]), "r"(a[2]), "r"(a[3]), "r"(b0), "r"(b1));
}
__device__ __forceinline__ void sts64(uint32_t addr, float a, float b) {
    asm volatile("st.shared.v2.f32 [%0], {%1,%2};" :: "r"(addr), "f"(a), "f"(b) : "memory");
}
__device__ __forceinline__ void lds128(float4& v, uint32_t addr) {
    asm volatile("ld.shared.v4.f32 {%0,%1,%2,%3}, [%4];"
        : "=f"(v.x), "=f"(v.y), "=f"(v.z), "=f"(v.w) : "r"(addr));
}
__device__ __forceinline__ void sts128(uint32_t addr, const uint32_t r[4]) {
    asm volatile("st.shared.v4.b32 [%0], {%1,%2,%3,%4};"
        :: "r"(addr), "r"(r[0]), "r"(r[1]), "r"(r[2]), "r"(r[3]) : "memory");
}

#define BAR_ARRIVE(id, cnt) asm volatile("bar.arrive %0, %1;" :: "r"(id), "r"(cnt) : "memory")
#define BAR_SYNC(id, cnt)   asm volatile("bar.sync %0, %1;"   :: "r"(id), "r"(cnt) : "memory")

// ---------------- SMEM layout (bytes from 1024-aligned base) ----------------
#define GT_JS 272         // Gt j-stride in words
#define W_HALF 36864      // 256 rows x 144B
#define OFF_H    0        // h: [l:4][m:64][k:72] fp16 = 36864 (144B rows)
#define OFF_W    36864    // bufA + bufB = 73728
#define OFF_GT   110592   // 64*272*4 = 69632
#define OFF_BIAS 180224   // [4][256] f32 (n'=4j+g order) = 4096
#define OFF_WI0  184320   // [256][3] f32 = 3072
#define OFF_WO   187392   // [3][64] f32 = 768
#define OFF_BO   188160   // 16
#define OFF_X    188176   // [3][64] f32 = 768
#define OFF_HT3  188944   // ht3[j:64][b:64] fp16 = 8192 (transposed h3 for pred)
#define SMEM_USE 197136
#define SMEM_REQ (SMEM_USE + 1024)

// ---------------- single prologue: weight repack + decoder_fc ----------------
__global__ void prologue_k(const float* __restrict__ conds,
                           const float* __restrict__ W1, const float* __restrict__ b1,
                           const float* __restrict__ W2, const float* __restrict__ b2,
                           const float* __restrict__ W_hh, const float* __restrict__ W_ih_rest) {
    const int b = blockIdx.x;
    const int t = threadIdx.x;  // 128

    // ---- repack slice (blocks 0..1151) ----
    int idx = b * 128 + t;
    if (idx < 4 * 2 * 256 * 72) {
        int kc = idx % 72, r = (idx / 72) & 255;
        int half = (idx / (72 * 256)) & 1, l = idx / (72 * 512);
        float v = 0.f;
        if (kc < 64) {
            int j = r >> 2, g = r & 3, n = g * 64 + j;
            if (half == 0)    v = W_hh[(l * 256 + n) * 64 + kc];
            else if (l > 0)   v = W_ih_rest[((l - 1) * 256 + n) * 64 + kc];
        }
        g_wm[l][half][r][kc] = __float2half(v);
    }

    // ---- embed for batch row b ----
    __shared__ float hid[64];
    __shared__ float cnd[8];
    if (t < 8) cnd[t] = conds[b * 8 + t];
    __syncthreads();
    if (t < 64) {
        float a = b1[t];
        #pragma unroll
        for (int k = 0; k < 8; k++) a += cnd[k] * W1[t * 8 + k];
        hid[t] = fmaxf(a, 0.f);
    }
    __syncthreads();
    float a = b2[t];
    #pragma unroll
    for (int k = 0; k < 64; k++) a += hid[k] * W2[t * 64 + k];
    g_init[(size_t)b * 128 + t] = a;
}

// stage one W half-image (36864 B) — MMA threads (tid<256).
// (l==0, half==1) is identically zero: skip the copies but keep the
// commit_group so the 2-outstanding wait accounting is unchanged.
__device__ __forceinline__ void stageWh(uint32_t dst, int l, int half, int tid) {
    if (!(l == 0 && half == 1)) {
        const char* src = (const char*)&g_wm[l][half][0][0];
        #pragma unroll
        for (int n = 0; n < 9; n++)
            cp16(dst + (uint32_t)(tid * 16 + n * 4096), src + tid * 16 + n * 4096);
    }
    cp_commit();
}

// One K=64 block: A from h (144B rows), B from a W half-buffer (144B rows).
#define CHUNK1(ABASE, WBASE)                                                           \
{                                                                                      \
    _Pragma("unroll")                                                                  \
    for (int ki = 0; ki < 4; ki++) {                                                   \
        uint32_t ah_[2][4];                                                            \
        _Pragma("unroll")                                                              \
        for (int mt = 0; mt < 2; mt++)                                                 \
            ldsm4(ah_[mt], (ABASE) + (uint32_t)((m0w + mt * 16) * 144 + ki * 32) + laneoff); \
        _Pragma("unroll")                                                              \
        for (int np = 0; np < 4; np++) {                                               \
            uint32_t bf_[4];                                                           \
            ldsm4(bf_, (WBASE) + (uint32_t)((n0w + np * 16) * 144 + ki * 32) + laneoff); \
            _Pragma("unroll")                                                          \
            for (int mt = 0; mt < 2; mt++) {                                           \
                mma16816(acc[mt][2 * np],     ah_[mt], bf_[0], bf_[2]);                \
                mma16816(acc[mt][2 * np + 1], ah_[mt], bf_[1], bf_[3]);                \
            }                                                                          \
        }                                                                              \
    }                                                                                  \
}

// EPI half: HALF=0 -> j = jg*8 + jj (jj 0..7); HALF=1 -> j = 32 + jg*8 + (jj-8)
// At L==3 also writes the transposed ht3[j][b] copy used by pred (conflict-free read).
#define EPI_H(L, CR, HALF)                                                             \
{                                                                                      \
    float x0 = 0.f, x1 = 0.f, x2 = 0.f;                                                \
    if ((L) == 0) { x0 = xS[b]; x1 = xS[64 + b]; x2 = xS[128 + b]; }                   \
    uint32_t hh[4];                                                                    \
    _Pragma("unroll")                                                                  \
    for (int jj = (HALF) * 8; jj < (HALF) * 8 + 8; jj++) {                             \
        int j = (HALF) * 32 + jg * 8 + (jj - (HALF) * 8);                              \
        float4 gv;                                                                     \
        lds128(gv, gtS + (uint32_t)((j * GT_JS + b * 4) * 4));                         \
        float vi = gv.x, vf = gv.y, vg = gv.z, vo = gv.w;                              \
        if ((L) == 0) {                                                                \
            vi += x0 * wi0S[j * 3] + x1 * wi0S[j * 3 + 1] + x2 * wi0S[j * 3 + 2];      \
            vf += x0 * wi0S[(64 + j) * 3] + x1 * wi0S[(64 + j) * 3 + 1] + x2 * wi0S[(64 + j) * 3 + 2];   \
            vg += x0 * wi0S[(128 + j) * 3] + x1 * wi0S[(128 + j) * 3 + 1] + x2 * wi0S[(128 + j) * 3 + 2]; \
            vo += x0 * wi0S[(192 + j) * 3] + x1 * wi0S[(192 + j) * 3 + 1] + x2 * wi0S[(192 + j) * 3 + 2]; \
        }                                                                              \
        float cn = sigm(vf) * CR[jj] + sigm(vi) * tanh_(vg);                           \
        CR[jj] = cn;                                                                   \
        float hn = sigm(vo) * tanh_(cn);                                               \
        __half hx = __float2half(hn);                                                  \
        if ((L) == 3) ht3E[j * 64 + b] = hx;                                           \
        uint32_t hu = (uint32_t)__half_as_ushort(hx);                                  \
        int u = jj - (HALF) * 8;                                                       \
        if (u & 1) hh[u >> 1] |= hu << 16; else hh[u >> 1] = hu;                       \
    }                                                                                  \
    sts128(hS + (uint32_t)(((L) * 64 + b) * 144 + (HALF) * 64 + jg * 16), hh);         \
}

__global__ __launch_bounds__(512, 1)
void lstm_main(const float* __restrict__ b_ih, const float* __restrict__ b_hh,
               const float* __restrict__ W_ih0,
               const float* __restrict__ Wo, const float* __restrict__ bo,
               float* __restrict__ out, int T) {
    extern __shared__ char raw[];
    char* basep = (char*)(((uintptr_t)raw + 1023) & ~(uintptr_t)1023);
    const uint32_t hS  = s32(basep + OFF_H);
    const uint32_t wA  = s32(basep + OFF_W);
    const uint32_t wB  = wA + W_HALF;
    const uint32_t gtS = s32(basep + OFF_GT);
    __half* hE   = (__half*)(basep + OFF_H);
    __half* ht3E = (__half*)(basep + OFF_HT3);
    float* biasS = (float*)(basep + OFF_BIAS);
    float* wi0S  = (float*)(basep + OFF_WI0);
    float* woS   = (float*)(basep + OFF_WO);
    float* boS   = (float*)(basep + OFF_BO);
    float* xS    = (float*)(basep + OFF_X);

    const int tid = threadIdx.x;
    const int bb0 = blockIdx.x * 64;

    // ---- stage small params (all 512 threads) ----
    for (int i = tid; i < 1024; i += 512) {
        int l = i >> 8, n = i & 255, g = n >> 6, j = n & 63;
        biasS[l * 256 + 4 * j + g] = b_ih[i] + b_hh[i];
    }
    for (int i = tid; i < 768;  i += 512) wi0S[i] = W_ih0[i];
    if (tid < 192) woS[tid] = Wo[tid];
    if (tid < 3)   boS[tid] = bo[tid];
    if (tid < 64)  { xS[tid] = 0.5f; xS[64 + tid] = 0.5f; xS[128 + tid] = 0.f; }

    // c-state lives in EPI warps (tid >= 256); mapping matches EPI_H
    float cr0[16], cr1[16], cr2[16], cr3[16];
    if (tid >= 256) {
        const int etid = tid - 256;
        const int b = etid & 63, jg = etid >> 6;
        #pragma unroll
        for (int jj = 0; jj < 16; jj++) {
            int j = (jj < 8) ? (jg * 8 + jj) : (32 + jg * 8 + jj - 8);
            float hv = g_init[(size_t)(bb0 + b) * 128 + j];
            float cv = g_init[(size_t)(bb0 + b) * 128 + 64 + j];
            cr0[jj] = cv; cr1[jj] = cv; cr2[jj] = cv; cr3[jj] = cv;
            __half bh = __float2half(hv);
            #pragma unroll
            for (int l = 0; l < 4; l++) hE[(l * 64 + b) * 72 + j] = bh;
        }
    }
    if (tid < 256) {       // prime: A(0), B(0)  -> 2 groups outstanding
        stageWh(wA, 0, 0, tid);
        stageWh(wB, 0, 1, tid);
    }
    __syncthreads();

    if (tid < 256) {
        // ================= MMA group (warps 0-7) =================
        const int lane = tid & 31, wid = tid >> 5;
        const int m0w = (wid & 1) * 32;
        const int n0w = (wid >> 1) * 64;
        const int sel = lane >> 3, lrow = lane & 7;
        const uint32_t laneoff = (uint32_t)(((sel & 1) * 8 + lrow) * 144 + (sel >> 1) * 16);
        const int gid = lane >> 2, tig = lane & 3;
        const bool loN = (wid < 4);   // owns cols 0..127 (units j<32)

        for (int t = 0; t < T; t++) {
            for (int l = 0; l < 4; l++) {
                const bool last = (t == T - 1 && l == 3);
                const int lnxt = (l + 1) & 3;

                cp_wait1();                 // A(l) resident (outstanding: A(l), B(l))
                BAR_SYNC(3, 256);

                // acc init = bias (per-column, fp32)
                float acc[2][8][4];
                #pragma unroll
                for (int nt = 0; nt < 8; nt++) {
                    int col = n0w + nt * 8 + 2 * tig;
                    float b0 = biasS[l * 256 + col];
                    float b1 = biasS[l * 256 + col + 1];
                    #pragma unroll
                    for (int mt = 0; mt < 2; mt++) {
                        acc[mt][nt][0] = b0; acc[mt][nt][1] = b1;
                        acc[mt][nt][2] = b0; acc[mt][nt][3] = b1;
                    }
                }

                // recurrent half: A = h[l] (t-1)
                CHUNK1(hS + (uint32_t)(l * 9216), wA);

                BAR_SYNC(3, 256);           // all MMA warps done reading bufA
                if (!last) stageWh(wA, lnxt, 0, tid);   // A(l+1)

                if (last) cp_wait0(); else cp_wait1();  // B(l) resident
                BAR_SYNC(2, 512);           // EPI(l-1) done (also syncs MMA group)

                // input half: A = h[l-1] (fresh)
                if (l > 0)
                    CHUNK1(hS + (uint32_t)((l - 1) * 9216), wB);

                // write gate pre-activations: Gt2[j][b][gate] via STS.64
                #pragma unroll
                for (int mt = 0; mt < 2; mt++)
                    #pragma unroll
                    for (int nt = 0; nt < 8; nt++) {
                        int col = n0w + nt * 8 + 2 * tig;
                        int j = col >> 2, g = col & 3;
                        int row = m0w + mt * 16 + gid;
                        uint32_t a0 = gtS + (uint32_t)((j * GT_JS + row * 4 + g) * 4);
                        sts64(a0,       acc[mt][nt][0], acc[mt][nt][1]);
                        sts64(a0 + 128, acc[mt][nt][2], acc[mt][nt][3]);   // row+8
                    }
                if (loN) BAR_ARRIVE(5, 384);   // Gt half j<32 ready
                else     BAR_ARRIVE(6, 384);   // Gt half j>=32 ready

                BAR_SYNC(3, 256);           // all MMA warps done reading bufB
                if (!last) stageWh(wB, lnxt, 1, tid);   // B(l+1)
            }
        }
    } else {
        // ================= EPI group (warps 8-15) =================
        const int etid = tid - 256;
        const int b = etid & 63, jg = etid >> 6;

        BAR_ARRIVE(2, 512);                 // prime: "EPI(-1) done"
        for (int t = 0; t < T; t++) {
            for (int l = 0; l < 4; l++) {
                BAR_SYNC(5, 384);           // Gt half j<32 ready
                switch (l) {
                    case 0: EPI_H(0, cr0, 0); break;
                    case 1: EPI_H(1, cr1, 0); break;
                    case 2: EPI_H(2, cr2, 0); break;
                    default: EPI_H(3, cr3, 0); break;
                }
                BAR_SYNC(6, 384);           // Gt half j>=32 ready
                switch (l) {
                    case 0: EPI_H(0, cr0, 1); break;
                    case 1: EPI_H(1, cr1, 1); break;
                    case 2: EPI_H(2, cr2, 1); break;
                    default: EPI_H(3, cr3, 1); break;
                }
                if (l == 3) {
                    BAR_SYNC(4, 256);       // h3/ht3 visible across EPI warps
                    if (etid < 192) {
                        int jo = etid >> 6;
                        float a = boS[jo];
                        #pragma unroll 8
                        for (int j = 0; j < 64; j++)
                            a += woS[jo * 64 + j] * __half2float(ht3E[j * 64 + b]);
                        out[(size_t)(bb0 + b) * (3 * T) + (size_t)t * 3 + jo] = a;
                        xS[jo * 64 + b] = a;
                    }
                }
                BAR_ARRIVE(2, 512);         // EPI(l) done
            }
        }
    }
}

// ---------------- entry ----------------
extern "C" void kernel_launch(void* const* d_in, const int* in_sizes, int n_in,
                              void* d_out, int out_size) {
    const float* conds     = (const float*)d_in[0];
    const float* W1        = (const float*)d_in[1];
    const float* b1        = (const float*)d_in[2];
    const float* W2        = (const float*)d_in[3];
    const float* b2        = (const float*)d_in[4];
    const float* W_ih0     = (const float*)d_in[5];
    const float* W_ih_rest = (const float*)d_in[6];
    const float* W_hh      = (const float*)d_in[7];
    const float* b_ih      = (const float*)d_in[8];
    const float* b_hh      = (const float*)d_in[9];
    const float* Wo        = (const float*)d_in[10];
    const float* bo        = (const float*)d_in[11];

    int B = in_sizes[0] / 8;
    if (B > B_MAX) B = B_MAX;
    int T = out_size / (B * 3);

    cudaFuncSetAttribute(lstm_main, cudaFuncAttributeMaxDynamicSharedMemorySize, SMEM_REQ);

    prologue_k<<<B, 128>>>(conds, W1, b1, W2, b2, W_hh, W_ih_rest);
    lstm_main<<<B / 64, 512, SMEM_REQ>>>(b_ih, b_hh, W_ih0, Wo, bo, (float*)d_out, T);
}